// round 1
// baseline (speedup 1.0000x reference)
#include <cuda_runtime.h>
#include <math.h>

#define TOKENS 131072
#define CD 120

// -------- scratch (device globals; aliased by lifetime) --------
__device__ float g_bufA[131072 * 720];  // qkv (720) -> later mlp pre-act (480)
__device__ float g_bufB[131072 * 240];  // attn concat (240) -> later gated hid (240)
__device__ float g_bufC[131072 * 120];  // xw (LN1+partition) -> later h2 (LN2)
__device__ float g_xres[131072 * 120];  // residual after proj

// ---------------- LayerNorm (+ optional window partition scatter) ----------------
__global__ void ln_kernel(const float* __restrict__ x, const float* __restrict__ w,
                          const float* __restrict__ b, float* __restrict__ out,
                          int partition)
{
    int warp = (blockIdx.x * blockDim.x + threadIdx.x) >> 5;
    int lane = threadIdx.x & 31;
    if (warp >= TOKENS) return;
    const float* xi = x + (size_t)warp * CD;
    float v[4];
    float s = 0.f;
#pragma unroll
    for (int i = 0; i < 4; i++) {
        int c = lane + 32 * i;
        v[i] = (c < CD) ? xi[c] : 0.f;
        s += v[i];
    }
#pragma unroll
    for (int o = 16; o > 0; o >>= 1) s += __shfl_xor_sync(0xffffffffu, s, o);
    float mean = s * (1.f / 120.f);
    float s2 = 0.f;
#pragma unroll
    for (int i = 0; i < 4; i++) {
        int c = lane + 32 * i;
        float d = (c < CD) ? (v[i] - mean) : 0.f;
        s2 += d * d;
    }
#pragma unroll
    for (int o = 16; o > 0; o >>= 1) s2 += __shfl_xor_sync(0xffffffffu, s2, o);
    float rstd = rsqrtf(s2 * (1.f / 120.f) + 1e-5f);

    int outrow = warp;
    if (partition) {
        int g = warp;
        int ww = g & 63, hh = (g >> 6) & 63, dd = (g >> 12) & 3, nn = g >> 14;
        int bwin = (((nn >> 1) * 2 + (dd >> 1)) * 8 + (hh >> 3)) * 8 + (ww >> 3);
        int t = (((nn & 1) * 2 + (dd & 1)) * 8 + (hh & 7)) * 8 + (ww & 7);
        outrow = bwin * 256 + t;
    }
    float* o = out + (size_t)outrow * CD;
#pragma unroll
    for (int i = 0; i < 4; i++) {
        int c = lane + 32 * i;
        if (c < CD) o[c] = (v[i] - mean) * rstd * w[c] + b[c];
    }
}

// ---------------- generic tiled GEMM: C = A[M,K] @ W[N,K]^T + bias ----------------
// EPI 0: store to Cout[row*ldo + col_off + col]
// EPI 1: proj epilogue: window-reverse scatter + residual (x input), 120 wide
// EPI 2: same-row residual add: Cout[row*ldo+col] = resid[row*ldo+col] + v
#define BM 128
#define BN 64
#define KC 60
#define PAD 4

template <int EPI>
__global__ void __launch_bounds__(256) gemm_kernel(
    const float* __restrict__ A, const float* __restrict__ W,
    const float* __restrict__ bias, float* __restrict__ Cout,
    const float* __restrict__ resid,
    int N, int K, int ldo, int col_off)
{
    __shared__ float As[KC][BM + PAD];
    __shared__ float Bs[KC][BN + PAD];
    int tid = threadIdx.x;
    int tx = tid & 15, ty = tid >> 4;
    int row0 = blockIdx.x * BM;
    int n0 = blockIdx.y * BN;
    float acc[8][4];
#pragma unroll
    for (int i = 0; i < 8; i++)
#pragma unroll
        for (int j = 0; j < 4; j++) acc[i][j] = 0.f;

    for (int kk = 0; kk < K; kk += KC) {
        // A tile: BM rows x KC k's (15 float4 per row)
        for (int i = tid; i < BM * (KC / 4); i += 256) {
            int m = i / (KC / 4), kq = i % (KC / 4);
            float4 f = *(const float4*)(A + (size_t)(row0 + m) * K + kk + kq * 4);
            As[kq * 4 + 0][m] = f.x;
            As[kq * 4 + 1][m] = f.y;
            As[kq * 4 + 2][m] = f.z;
            As[kq * 4 + 3][m] = f.w;
        }
        // B tile: Bs[k][n] = W[(n0+n)*K + kk + k]
        for (int i = tid; i < BN * (KC / 4); i += 256) {
            int n = i / (KC / 4), kq = i % (KC / 4);
            float4 f = make_float4(0.f, 0.f, 0.f, 0.f);
            if (n0 + n < N) f = *(const float4*)(W + (size_t)(n0 + n) * K + kk + kq * 4);
            Bs[kq * 4 + 0][n] = f.x;
            Bs[kq * 4 + 1][n] = f.y;
            Bs[kq * 4 + 2][n] = f.z;
            Bs[kq * 4 + 3][n] = f.w;
        }
        __syncthreads();
#pragma unroll 4
        for (int k = 0; k < KC; k++) {
            float4 b4 = *(const float4*)&Bs[k][tx * 4];
            float4 a0 = *(const float4*)&As[k][ty * 8];
            float4 a1 = *(const float4*)&As[k][ty * 8 + 4];
            float a[8] = {a0.x, a0.y, a0.z, a0.w, a1.x, a1.y, a1.z, a1.w};
            float bb[4] = {b4.x, b4.y, b4.z, b4.w};
#pragma unroll
            for (int i = 0; i < 8; i++)
#pragma unroll
                for (int j = 0; j < 4; j++) acc[i][j] += a[i] * bb[j];
        }
        __syncthreads();
    }

#pragma unroll
    for (int i = 0; i < 8; i++) {
        int row = row0 + ty * 8 + i;
#pragma unroll
        for (int j = 0; j < 4; j++) {
            int col = n0 + tx * 4 + j;
            if (col >= N) continue;
            float v = acc[i][j] + bias[col];
            if (EPI == 0) {
                Cout[(size_t)row * ldo + col_off + col] = v;
            } else if (EPI == 1) {
                int bwin = row >> 8, t = row & 255;
                int ww = bwin & 7, wh = (bwin >> 3) & 7, wd = (bwin >> 6) & 1, wn = bwin >> 7;
                int iw = t & 7, ih = (t >> 3) & 7, id = (t >> 6) & 1, inn = t >> 7;
                int n_ = wn * 2 + inn, d_ = wd * 2 + id, h_ = wh * 8 + ih, w_ = ww * 8 + iw;
                int gidx = ((n_ * 4 + d_) * 64 + h_) * 64 + w_;
                Cout[(size_t)gidx * 120 + col] = resid[(size_t)gidx * 120 + col] + v;
            } else {
                Cout[(size_t)row * ldo + col] = resid[(size_t)row * ldo + col] + v;
            }
        }
    }
}

// ---------------- attention: one thread per query, online softmax ----------------
// qkv layout per row (720): [0,360) self, [360,720) mut; within a section:
// q at h*20, k at 120+h*20, v at 240+h*20.
__global__ void attn_kernel(const float* __restrict__ qkv, float* __restrict__ out,
                            int sec, int q_row_off, int kv_row_off, int o_row_off,
                            int nk, int out_col_off)
{
    __shared__ float Ks[256 * 20];
    __shared__ float Vs[256 * 20];
    int bwin = blockIdx.x, h = blockIdx.y;
    int base = bwin * 256;
    int tid = threadIdx.x;
    int qcol = sec + h * 20, kcol = sec + 120 + h * 20, vcol = sec + 240 + h * 20;

    for (int i = tid; i < nk * 20; i += blockDim.x) {
        int r = i / 20, c = i % 20;
        size_t rowidx = (size_t)(base + kv_row_off + r) * 720;
        Ks[i] = qkv[rowidx + kcol + c];
        Vs[i] = qkv[rowidx + vcol + c];
    }
    __syncthreads();

    const float scale = 0.22360679774997896f;  // 20^-0.5
    float q[20], o[20];
    const float* qr = qkv + (size_t)(base + q_row_off + tid) * 720 + qcol;
#pragma unroll
    for (int c = 0; c < 20; c++) { q[c] = qr[c] * scale; o[c] = 0.f; }
    float m = -1e30f, l = 0.f;
    for (int j = 0; j < nk; j++) {
        float s = 0.f;
#pragma unroll
        for (int c = 0; c < 20; c++) s += q[c] * Ks[j * 20 + c];
        float mn = fmaxf(m, s);
        float f = __expf(m - mn);
        float p = __expf(s - mn);
        l = l * f + p;
#pragma unroll
        for (int c = 0; c < 20; c++) o[c] = o[c] * f + p * Vs[j * 20 + c];
        m = mn;
    }
    float inv = 1.f / l;
    float* op = out + (size_t)(base + o_row_off + tid) * 240 + out_col_off + h * 20;
#pragma unroll
    for (int c = 0; c < 20; c++) op[c] = o[c] * inv;
}

// ---------------- GEGLU gate: hid = gelu_exact(g) * u ----------------
__global__ void gate_kernel(const float* __restrict__ t, float* __restrict__ out, int total)
{
    int i = blockIdx.x * blockDim.x + threadIdx.x;
    if (i >= total) return;
    int row = i / 240, j = i % 240;
    float g = t[(size_t)row * 480 + j];
    float u = t[(size_t)row * 480 + 240 + j];
    float ge = 0.5f * g * (1.f + erff(g * 0.70710678118654752f));
    out[i] = ge * u;
}

extern "C" void kernel_launch(void* const* d_in, const int* in_sizes, int n_in,
                              void* d_out, int out_size)
{
    const float* x          = (const float*)d_in[0];
    const float* norm1_w    = (const float*)d_in[1];
    const float* norm1_b    = (const float*)d_in[2];
    const float* qkv_self_w = (const float*)d_in[3];
    const float* qkv_self_b = (const float*)d_in[4];
    const float* qkv_mut_w  = (const float*)d_in[5];
    const float* qkv_mut_b  = (const float*)d_in[6];
    const float* proj_w     = (const float*)d_in[7];
    const float* proj_b     = (const float*)d_in[8];
    const float* norm2_w    = (const float*)d_in[9];
    const float* norm2_b    = (const float*)d_in[10];
    const float* fc11_w     = (const float*)d_in[11];
    const float* fc11_b     = (const float*)d_in[12];
    const float* fc12_w     = (const float*)d_in[13];
    const float* fc12_b     = (const float*)d_in[14];
    const float* fc2_w      = (const float*)d_in[15];
    const float* fc2_b      = (const float*)d_in[16];

    float *bufA, *bufB, *bufC, *xres;
    cudaGetSymbolAddress((void**)&bufA, g_bufA);
    cudaGetSymbolAddress((void**)&bufB, g_bufB);
    cudaGetSymbolAddress((void**)&bufC, g_bufC);
    cudaGetSymbolAddress((void**)&xres, g_xres);

    const int M = TOKENS;

    // 1) LN1 + window partition -> bufC (xw)
    ln_kernel<<<M / 8, 256>>>(x, norm1_w, norm1_b, bufC, 1);

    // 2) qkv_self / qkv_mut GEMMs -> bufA [M,720]
    {
        dim3 g(M / BM, (360 + BN - 1) / BN);
        gemm_kernel<0><<<g, 256>>>(bufC, qkv_self_w, qkv_self_b, bufA, nullptr, 360, 120, 720, 0);
        gemm_kernel<0><<<g, 256>>>(bufC, qkv_mut_w,  qkv_mut_b,  bufA, nullptr, 360, 120, 720, 360);
    }

    // 3) attention -> bufB [M,240] (cols 0..119 mutual, 120..239 self)
    attn_kernel<<<dim3(512, 6), 256>>>(bufA, bufB, 0,   0,   0,   0,   256, 120);  // self
    attn_kernel<<<dim3(512, 6), 128>>>(bufA, bufB, 360, 128, 0,   0,   128, 0);    // x1 = mha(q2,k1,v1)
    attn_kernel<<<dim3(512, 6), 128>>>(bufA, bufB, 360, 0,   128, 128, 128, 0);    // x2 = mha(q1,k2,v2)

    // 4) proj GEMM + window reverse + residual -> xres [M,120] (original layout)
    {
        dim3 g(M / BM, (120 + BN - 1) / BN);
        gemm_kernel<1><<<g, 256>>>(bufB, proj_w, proj_b, xres, x, 120, 240, 120, 0);
    }

    // 5) LN2 -> bufC (h2)
    ln_kernel<<<M / 8, 256>>>(xres, norm2_w, norm2_b, bufC, 0);

    // 6) fc11 / fc12 GEMMs -> bufA [M,480]
    {
        dim3 g(M / BM, (240 + BN - 1) / BN);
        gemm_kernel<0><<<g, 256>>>(bufC, fc11_w, fc11_b, bufA, nullptr, 240, 120, 480, 0);
        gemm_kernel<0><<<g, 256>>>(bufC, fc12_w, fc12_b, bufA, nullptr, 240, 120, 480, 240);
    }

    // 7) GEGLU gate -> bufB [M,240]
    {
        int total = M * 240;
        gate_kernel<<<(total + 255) / 256, 256>>>(bufA, bufB, total);
    }

    // 8) fc2 GEMM + residual -> d_out
    {
        dim3 g(M / BM, (120 + BN - 1) / BN);
        gemm_kernel<2><<<g, 256>>>(bufB, fc2_w, fc2_b, (float*)d_out, xres, 120, 240, 120, 0);
    }
}

// round 2
// speedup vs baseline: 1.2944x; 1.2944x over previous
#include <cuda_runtime.h>
#include <math.h>

#define TOKENS 131072
#define CD 120

typedef unsigned long long u64;

__device__ __forceinline__ u64 pk2(float lo, float hi) {
    u64 r; asm("mov.b64 %0, {%1,%2};" : "=l"(r) : "f"(lo), "f"(hi)); return r;
}
__device__ __forceinline__ void upk2(u64 v, float& lo, float& hi) {
    asm("mov.b64 {%0,%1}, %2;" : "=f"(lo), "=f"(hi) : "l"(v));
}
__device__ __forceinline__ u64 ffma2(u64 a, u64 b, u64 c) {
    u64 d; asm("fma.rn.f32x2 %0, %1, %2, %3;" : "=l"(d) : "l"(a), "l"(b), "l"(c)); return d;
}
__device__ __forceinline__ u64 fmul2(u64 a, u64 b) {
    u64 d; asm("mul.rn.f32x2 %0, %1, %2;" : "=l"(d) : "l"(a), "l"(b)); return d;
}

// -------- scratch (device globals; aliased by lifetime) --------
__device__ float g_bufA[131072 * 720];  // qkv (720) -> later mlp pre-act (480)
__device__ float g_bufB[131072 * 240];  // attn concat (240) -> later gated hid (240)
__device__ float g_bufC[131072 * 120];  // xw (LN1+partition) -> later h2 (LN2)
__device__ float g_xres[131072 * 120];  // residual after proj

// ---------------- LayerNorm (+ optional window partition scatter) ----------------
__global__ void ln_kernel(const float* __restrict__ x, const float* __restrict__ w,
                          const float* __restrict__ b, float* __restrict__ out,
                          int partition)
{
    int warp = (blockIdx.x * blockDim.x + threadIdx.x) >> 5;
    int lane = threadIdx.x & 31;
    if (warp >= TOKENS) return;
    const float* xi = x + (size_t)warp * CD;
    float v[4];
    float s = 0.f;
#pragma unroll
    for (int i = 0; i < 4; i++) {
        int c = lane + 32 * i;
        v[i] = (c < CD) ? xi[c] : 0.f;
        s += v[i];
    }
#pragma unroll
    for (int o = 16; o > 0; o >>= 1) s += __shfl_xor_sync(0xffffffffu, s, o);
    float mean = s * (1.f / 120.f);
    float s2 = 0.f;
#pragma unroll
    for (int i = 0; i < 4; i++) {
        int c = lane + 32 * i;
        float d = (c < CD) ? (v[i] - mean) : 0.f;
        s2 += d * d;
    }
#pragma unroll
    for (int o = 16; o > 0; o >>= 1) s2 += __shfl_xor_sync(0xffffffffu, s2, o);
    float rstd = rsqrtf(s2 * (1.f / 120.f) + 1e-5f);

    int outrow = warp;
    if (partition) {
        int g = warp;
        int ww = g & 63, hh = (g >> 6) & 63, dd = (g >> 12) & 3, nn = g >> 14;
        int bwin = (((nn >> 1) * 2 + (dd >> 1)) * 8 + (hh >> 3)) * 8 + (ww >> 3);
        int t = (((nn & 1) * 2 + (dd & 1)) * 8 + (hh & 7)) * 8 + (ww & 7);
        outrow = bwin * 256 + t;
    }
    float* o = out + (size_t)outrow * CD;
#pragma unroll
    for (int i = 0; i < 4; i++) {
        int c = lane + 32 * i;
        if (c < CD) o[c] = (v[i] - mean) * rstd * w[c] + b[c];
    }
}

// ---------------- GEMM v2: C = A[M,K] @ W[N,K]^T + bias, f32x2 math ----------------
// BM=128, BN=128, BK=20, 256 threads, 8x8 per thread, double-buffered smem.
// EPI 0: store to Cout[row*ldo + col_off + col]
// EPI 1: proj epilogue: window-reverse scatter + residual, width 120
// EPI 2: same-row residual add
#define BM 128
#define BN 128
#define BK 20

template <int EPI>
__global__ void __launch_bounds__(256, 2) gemm_kernel(
    const float* __restrict__ A, const float* __restrict__ W,
    const float* __restrict__ bias, float* __restrict__ Cout,
    const float* __restrict__ resid,
    int N, int K, int ldo, int col_off)
{
    __shared__ float As[2][BK][BM + 4];
    __shared__ float Bs[2][BK][BN + 4];
    int tid = threadIdx.x;
    int tx = tid & 15, ty = tid >> 4;
    int row0 = blockIdx.x * BM;
    int n0 = blockIdx.y * BN;

    u64 acc[8][4];
#pragma unroll
    for (int i = 0; i < 8; i++)
#pragma unroll
        for (int j = 0; j < 4; j++) acc[i][j] = 0ull;

    const int T = K / BK;  // 6 or 12
    float4 ra[3], rb[3];

    // ---- load stage 0 into regs ----
    auto load_tile = [&](int t, float4* la, float4* lb) {
#pragma unroll
        for (int s = 0; s < 3; s++) {
            int f = tid + 256 * s;
            if (f < 640) {
                int m = f / 5, kq = f % 5;
                la[s] = *(const float4*)(A + (size_t)(row0 + m) * K + t * BK + kq * 4);
                int n = n0 + m;
                if (n < N)
                    lb[s] = *(const float4*)(W + (size_t)n * K + t * BK + kq * 4);
                else
                    lb[s] = make_float4(0.f, 0.f, 0.f, 0.f);
            }
        }
    };
    auto store_tile = [&](int b, const float4* la, const float4* lb) {
#pragma unroll
        for (int s = 0; s < 3; s++) {
            int f = tid + 256 * s;
            if (f < 640) {
                int m = f / 5, kq = f % 5;
                As[b][kq * 4 + 0][m] = la[s].x;
                As[b][kq * 4 + 1][m] = la[s].y;
                As[b][kq * 4 + 2][m] = la[s].z;
                As[b][kq * 4 + 3][m] = la[s].w;
                Bs[b][kq * 4 + 0][m] = lb[s].x;
                Bs[b][kq * 4 + 1][m] = lb[s].y;
                Bs[b][kq * 4 + 2][m] = lb[s].z;
                Bs[b][kq * 4 + 3][m] = lb[s].w;
            }
        }
    };

    load_tile(0, ra, rb);
    store_tile(0, ra, rb);
    __syncthreads();

    for (int t = 0; t < T; t++) {
        if (t + 1 < T) load_tile(t + 1, ra, rb);
        int b = t & 1;
#pragma unroll
        for (int k = 0; k < BK; k++) {
            float4 a0 = *(const float4*)&As[b][k][ty * 8];
            float4 a1 = *(const float4*)&As[b][k][ty * 8 + 4];
            float4 b0 = *(const float4*)&Bs[b][k][tx * 8];
            float4 b1 = *(const float4*)&Bs[b][k][tx * 8 + 4];
            u64 bp0 = pk2(b0.x, b0.y), bp1 = pk2(b0.z, b0.w);
            u64 bp2 = pk2(b1.x, b1.y), bp3 = pk2(b1.z, b1.w);
            float av[8] = {a0.x, a0.y, a0.z, a0.w, a1.x, a1.y, a1.z, a1.w};
#pragma unroll
            for (int i = 0; i < 8; i++) {
                u64 ai = pk2(av[i], av[i]);
                acc[i][0] = ffma2(ai, bp0, acc[i][0]);
                acc[i][1] = ffma2(ai, bp1, acc[i][1]);
                acc[i][2] = ffma2(ai, bp2, acc[i][2]);
                acc[i][3] = ffma2(ai, bp3, acc[i][3]);
            }
        }
        if (t + 1 < T) {
            __syncthreads();
            store_tile((t + 1) & 1, ra, rb);
            __syncthreads();
        }
    }

    // ---- epilogue ----
    float bl[4], bh[4];
#pragma unroll
    for (int jp = 0; jp < 4; jp++) {
        int col = n0 + tx * 8 + jp * 2;
        bl[jp] = (col < N) ? bias[col] : 0.f;
        bh[jp] = (col + 1 < N) ? bias[col + 1] : 0.f;
    }
#pragma unroll
    for (int i = 0; i < 8; i++) {
        int row = row0 + ty * 8 + i;
        size_t obase;
        const float* rbase = nullptr;
        if (EPI == 1) {
            int bwin = row >> 8, tt = row & 255;
            int ww = bwin & 7, wh = (bwin >> 3) & 7, wd = (bwin >> 6) & 1, wn = bwin >> 7;
            int iw = tt & 7, ih = (tt >> 3) & 7, id = (tt >> 6) & 1, inn = tt >> 7;
            int n_ = wn * 2 + inn, d_ = wd * 2 + id, h_ = wh * 8 + ih, w_ = ww * 8 + iw;
            int gidx = ((n_ * 4 + d_) * 64 + h_) * 64 + w_;
            obase = (size_t)gidx * 120;
            rbase = resid + obase;
        } else {
            obase = (size_t)row * ldo;
            if (EPI == 2) rbase = resid + obase;
        }
#pragma unroll
        for (int jp = 0; jp < 4; jp++) {
            int col = n0 + tx * 8 + jp * 2;
            if (col >= N) continue;
            float lo, hi;
            upk2(acc[i][jp], lo, hi);
            lo += bl[jp]; hi += bh[jp];
            if (EPI == 0) {
                if (col + 1 < N) {
                    float2 v = {lo, hi};
                    *(float2*)&Cout[obase + col_off + col] = v;
                } else {
                    Cout[obase + col_off + col] = lo;
                }
            } else {
                if (col + 1 < N) {
                    float2 r = *(const float2*)&rbase[col];
                    float2 v = {r.x + lo, r.y + hi};
                    *(float2*)&Cout[obase + col] = v;
                } else {
                    Cout[obase + col] = rbase[col] + lo;
                }
            }
        }
    }
}

// ---------------- attention v2: chunked online softmax, f32x2, float4 smem ----------------
// qkv layout per row (720): [0,360) self, [360,720) mut; within a section:
// q at h*20, k at 120+h*20, v at 240+h*20.
__global__ void attn_kernel(const float* __restrict__ qkv, float* __restrict__ out,
                            int sec, int q_row_off, int kv_row_off, int o_row_off,
                            int nk, int out_col_off)
{
    extern __shared__ float sm[];
    float* Ks = sm;
    float* Vs = sm + nk * 20;
    int bwin = blockIdx.x, h = blockIdx.y;
    int base = bwin * 256;
    int tid = threadIdx.x;
    int qcol = sec + h * 20, kcol = sec + 120 + h * 20, vcol = sec + 240 + h * 20;

    for (int i4 = tid; i4 < nk * 5; i4 += blockDim.x) {
        int r = i4 / 5, c4 = i4 % 5;
        size_t rowidx = (size_t)(base + kv_row_off + r) * 720;
        *(float4*)&Ks[r * 20 + c4 * 4] = *(const float4*)&qkv[rowidx + kcol + c4 * 4];
        *(float4*)&Vs[r * 20 + c4 * 4] = *(const float4*)&qkv[rowidx + vcol + c4 * 4];
    }
    __syncthreads();

    const float scale = 0.22360679774997896f;  // 20^-0.5
    u64 q2[10], o2[10];
    const float* qr = qkv + (size_t)(base + q_row_off + tid) * 720 + qcol;
#pragma unroll
    for (int t = 0; t < 5; t++) {
        float4 qv = *(const float4*)(qr + t * 4);
        q2[2 * t]     = pk2(qv.x * scale, qv.y * scale);
        q2[2 * t + 1] = pk2(qv.z * scale, qv.w * scale);
        o2[2 * t] = 0ull; o2[2 * t + 1] = 0ull;
    }
    float m = -1e30f, l = 0.f;

    for (int j0 = 0; j0 < nk; j0 += 8) {
        float s[8];
#pragma unroll
        for (int jj = 0; jj < 8; jj++) {
            const float* kr = &Ks[(j0 + jj) * 20];
            u64 acc = 0ull;
#pragma unroll
            for (int t = 0; t < 5; t++) {
                float4 kv = *(const float4*)(kr + t * 4);
                acc = ffma2(q2[2 * t],     pk2(kv.x, kv.y), acc);
                acc = ffma2(q2[2 * t + 1], pk2(kv.z, kv.w), acc);
            }
            float lo, hi; upk2(acc, lo, hi);
            s[jj] = lo + hi;
        }
        float cm = s[0];
#pragma unroll
        for (int jj = 1; jj < 8; jj++) cm = fmaxf(cm, s[jj]);
        float mn = fmaxf(m, cm);
        float f = __expf(m - mn);
        float p[8];
        float ls = 0.f;
#pragma unroll
        for (int jj = 0; jj < 8; jj++) { p[jj] = __expf(s[jj] - mn); ls += p[jj]; }
        l = l * f + ls;
        u64 f2 = pk2(f, f);
#pragma unroll
        for (int t = 0; t < 10; t++) o2[t] = fmul2(o2[t], f2);
#pragma unroll
        for (int jj = 0; jj < 8; jj++) {
            u64 p2 = pk2(p[jj], p[jj]);
            const float* vr = &Vs[(j0 + jj) * 20];
#pragma unroll
            for (int t = 0; t < 5; t++) {
                float4 v = *(const float4*)(vr + t * 4);
                o2[2 * t]     = ffma2(p2, pk2(v.x, v.y), o2[2 * t]);
                o2[2 * t + 1] = ffma2(p2, pk2(v.z, v.w), o2[2 * t + 1]);
            }
        }
        m = mn;
    }
    float inv = 1.f / l;
    u64 inv2 = pk2(inv, inv);
    float* op = out + (size_t)(base + o_row_off + tid) * 240 + out_col_off + h * 20;
#pragma unroll
    for (int t = 0; t < 10; t++) {
        float lo, hi; upk2(fmul2(o2[t], inv2), lo, hi);
        float2 v = {lo, hi};
        *(float2*)&op[2 * t] = v;
    }
}

// ---------------- GEGLU gate: hid = gelu_exact(g) * u ----------------
__global__ void gate_kernel(const float* __restrict__ t, float* __restrict__ out, int total)
{
    int i = blockIdx.x * blockDim.x + threadIdx.x;
    if (i >= total) return;
    int row = i / 240, j = i % 240;
    float g = t[(size_t)row * 480 + j];
    float u = t[(size_t)row * 480 + 240 + j];
    float ge = 0.5f * g * (1.f + erff(g * 0.70710678118654752f));
    out[i] = ge * u;
}

extern "C" void kernel_launch(void* const* d_in, const int* in_sizes, int n_in,
                              void* d_out, int out_size)
{
    const float* x          = (const float*)d_in[0];
    const float* norm1_w    = (const float*)d_in[1];
    const float* norm1_b    = (const float*)d_in[2];
    const float* qkv_self_w = (const float*)d_in[3];
    const float* qkv_self_b = (const float*)d_in[4];
    const float* qkv_mut_w  = (const float*)d_in[5];
    const float* qkv_mut_b  = (const float*)d_in[6];
    const float* proj_w     = (const float*)d_in[7];
    const float* proj_b     = (const float*)d_in[8];
    const float* norm2_w    = (const float*)d_in[9];
    const float* norm2_b    = (const float*)d_in[10];
    const float* fc11_w     = (const float*)d_in[11];
    const float* fc11_b     = (const float*)d_in[12];
    const float* fc12_w     = (const float*)d_in[13];
    const float* fc12_b     = (const float*)d_in[14];
    const float* fc2_w      = (const float*)d_in[15];
    const float* fc2_b      = (const float*)d_in[16];

    float *bufA, *bufB, *bufC, *xres;
    cudaGetSymbolAddress((void**)&bufA, g_bufA);
    cudaGetSymbolAddress((void**)&bufB, g_bufB);
    cudaGetSymbolAddress((void**)&bufC, g_bufC);
    cudaGetSymbolAddress((void**)&xres, g_xres);

    const int M = TOKENS;

    // 1) LN1 + window partition -> bufC (xw)
    ln_kernel<<<M / 8, 256>>>(x, norm1_w, norm1_b, bufC, 1);

    // 2) qkv_self / qkv_mut GEMMs -> bufA [M,720]
    {
        dim3 g(M / BM, 3);
        gemm_kernel<0><<<g, 256>>>(bufC, qkv_self_w, qkv_self_b, bufA, nullptr, 360, 120, 720, 0);
        gemm_kernel<0><<<g, 256>>>(bufC, qkv_mut_w,  qkv_mut_b,  bufA, nullptr, 360, 120, 720, 360);
    }

    // 3) attention -> bufB [M,240] (cols 0..119 mutual, 120..239 self)
    attn_kernel<<<dim3(512, 6), 256, 256 * 40 * 4>>>(bufA, bufB, 0,   0,   0,   0,   256, 120);  // self
    attn_kernel<<<dim3(512, 6), 128, 128 * 40 * 4>>>(bufA, bufB, 360, 128, 0,   0,   128, 0);    // x1 = mha(q2,k1,v1)
    attn_kernel<<<dim3(512, 6), 128, 128 * 40 * 4>>>(bufA, bufB, 360, 0,   128, 128, 128, 0);    // x2 = mha(q1,k2,v2)

    // 4) proj GEMM + window reverse + residual -> xres [M,120] (original layout)
    {
        dim3 g(M / BM, 1);
        gemm_kernel<1><<<g, 256>>>(bufB, proj_w, proj_b, xres, x, 120, 240, 120, 0);
    }

    // 5) LN2 -> bufC (h2)
    ln_kernel<<<M / 8, 256>>>(xres, norm2_w, norm2_b, bufC, 0);

    // 6) fc11 / fc12 GEMMs -> bufA [M,480]
    {
        dim3 g(M / BM, 2);
        gemm_kernel<0><<<g, 256>>>(bufC, fc11_w, fc11_b, bufA, nullptr, 240, 120, 480, 0);
        gemm_kernel<0><<<g, 256>>>(bufC, fc12_w, fc12_b, bufA, nullptr, 240, 120, 480, 240);
    }

    // 7) GEGLU gate -> bufB [M,240]
    {
        int total = M * 240;
        gate_kernel<<<(total + 255) / 256, 256>>>(bufA, bufB, total);
    }

    // 8) fc2 GEMM + residual -> d_out
    {
        dim3 g(M / BM, 1);
        gemm_kernel<2><<<g, 256>>>(bufB, fc2_w, fc2_b, (float*)d_out, xres, 120, 240, 120, 0);
    }
}

// round 7
// speedup vs baseline: 1.4042x; 1.0849x over previous
#include <cuda_runtime.h>
#include <math.h>

#define TOKENS 131072
#define CD 120

typedef unsigned long long u64;

__device__ __forceinline__ u64 pk2(float lo, float hi) {
    u64 r; asm("mov.b64 %0, {%1,%2};" : "=l"(r) : "f"(lo), "f"(hi)); return r;
}
__device__ __forceinline__ void upk2(u64 v, float& lo, float& hi) {
    asm("mov.b64 {%0,%1}, %2;" : "=f"(lo), "=f"(hi) : "l"(v));
}
__device__ __forceinline__ u64 ffma2(u64 a, u64 b, u64 c) {
    u64 d; asm("fma.rn.f32x2 %0, %1, %2, %3;" : "=l"(d) : "l"(a), "l"(b), "l"(c)); return d;
}
__device__ __forceinline__ u64 fmul2(u64 a, u64 b) {
    u64 d; asm("mul.rn.f32x2 %0, %1, %2;" : "=l"(d) : "l"(a), "l"(b)); return d;
}

// -------- scratch (device globals; aliased by lifetime) --------
__device__ float g_bufA[131072 * 720];  // qkv (720) -> later mlp pre-act (480)
__device__ float g_bufB[131072 * 240];  // attn concat (240) -> later gated hid (240)
__device__ float g_bufC[131072 * 120];  // xw (LN1+partition) -> later h2 (LN2)
__device__ float g_xres[131072 * 120];  // residual after proj

// ---------------- LayerNorm (+ optional window partition scatter) ----------------
__global__ void ln_kernel(const float* __restrict__ x, const float* __restrict__ w,
                          const float* __restrict__ b, float* __restrict__ out,
                          int partition)
{
    int warp = (blockIdx.x * blockDim.x + threadIdx.x) >> 5;
    int lane = threadIdx.x & 31;
    if (warp >= TOKENS) return;
    const float* xi = x + (size_t)warp * CD;
    float v[4];
    float s = 0.f;
#pragma unroll
    for (int i = 0; i < 4; i++) {
        int c = lane + 32 * i;
        v[i] = (c < CD) ? xi[c] : 0.f;
        s += v[i];
    }
#pragma unroll
    for (int o = 16; o > 0; o >>= 1) s += __shfl_xor_sync(0xffffffffu, s, o);
    float mean = s * (1.f / 120.f);
    float s2 = 0.f;
#pragma unroll
    for (int i = 0; i < 4; i++) {
        int c = lane + 32 * i;
        float d = (c < CD) ? (v[i] - mean) : 0.f;
        s2 += d * d;
    }
#pragma unroll
    for (int o = 16; o > 0; o >>= 1) s2 += __shfl_xor_sync(0xffffffffu, s2, o);
    float rstd = rsqrtf(s2 * (1.f / 120.f) + 1e-5f);

    int outrow = warp;
    if (partition) {
        int g = warp;
        int ww = g & 63, hh = (g >> 6) & 63, dd = (g >> 12) & 3, nn = g >> 14;
        int bwin = (((nn >> 1) * 2 + (dd >> 1)) * 8 + (hh >> 3)) * 8 + (ww >> 3);
        int t = (((nn & 1) * 2 + (dd & 1)) * 8 + (hh & 7)) * 8 + (ww & 7);
        outrow = bwin * 256 + t;
    }
    float* o = out + (size_t)outrow * CD;
#pragma unroll
    for (int i = 0; i < 4; i++) {
        int c = lane + 32 * i;
        if (c < CD) o[c] = (v[i] - mean) * rstd * w[c] + b[c];
    }
}

// ---------------- GEMM: C = A[M,K] @ W[N,K]^T + bias, f32x2 math ----------------
#define BM 128
#define BN 128
#define BK 20

template <int EPI>
__global__ void __launch_bounds__(256, 2) gemm_kernel(
    const float* __restrict__ A, const float* __restrict__ W,
    const float* __restrict__ bias, float* __restrict__ Cout,
    const float* __restrict__ resid,
    int N, int K, int ldo, int col_off)
{
    __shared__ float As[2][BK][BM + 4];
    __shared__ float Bs[2][BK][BN + 4];
    int tid = threadIdx.x;
    int tx = tid & 15, ty = tid >> 4;
    int row0 = blockIdx.x * BM;
    int n0 = blockIdx.y * BN;

    u64 acc[8][4];
#pragma unroll
    for (int i = 0; i < 8; i++)
#pragma unroll
        for (int j = 0; j < 4; j++) acc[i][j] = 0ull;

    const int T = K / BK;
    float4 ra[3], rb[3];

    auto load_tile = [&](int t, float4* la, float4* lb) {
#pragma unroll
        for (int s = 0; s < 3; s++) {
            int f = tid + 256 * s;
            if (f < 640) {
                int m = f / 5, kq = f % 5;
                la[s] = *(const float4*)(A + (size_t)(row0 + m) * K + t * BK + kq * 4);
                int n = n0 + m;
                if (n < N)
                    lb[s] = *(const float4*)(W + (size_t)n * K + t * BK + kq * 4);
                else
                    lb[s] = make_float4(0.f, 0.f, 0.f, 0.f);
            }
        }
    };
    auto store_tile = [&](int b, const float4* la, const float4* lb) {
#pragma unroll
        for (int s = 0; s < 3; s++) {
            int f = tid + 256 * s;
            if (f < 640) {
                int m = f / 5, kq = f % 5;
                As[b][kq * 4 + 0][m] = la[s].x;
                As[b][kq * 4 + 1][m] = la[s].y;
                As[b][kq * 4 + 2][m] = la[s].z;
                As[b][kq * 4 + 3][m] = la[s].w;
                Bs[b][kq * 4 + 0][m] = lb[s].x;
                Bs[b][kq * 4 + 1][m] = lb[s].y;
                Bs[b][kq * 4 + 2][m] = lb[s].z;
                Bs[b][kq * 4 + 3][m] = lb[s].w;
            }
        }
    };

    load_tile(0, ra, rb);
    store_tile(0, ra, rb);
    __syncthreads();

    for (int t = 0; t < T; t++) {
        if (t + 1 < T) load_tile(t + 1, ra, rb);
        int b = t & 1;
#pragma unroll
        for (int k = 0; k < BK; k++) {
            float4 a0 = *(const float4*)&As[b][k][ty * 8];
            float4 a1 = *(const float4*)&As[b][k][ty * 8 + 4];
            float4 b0 = *(const float4*)&Bs[b][k][tx * 8];
            float4 b1 = *(const float4*)&Bs[b][k][tx * 8 + 4];
            u64 bp0 = pk2(b0.x, b0.y), bp1 = pk2(b0.z, b0.w);
            u64 bp2 = pk2(b1.x, b1.y), bp3 = pk2(b1.z, b1.w);
            float av[8] = {a0.x, a0.y, a0.z, a0.w, a1.x, a1.y, a1.z, a1.w};
#pragma unroll
            for (int i = 0; i < 8; i++) {
                u64 ai = pk2(av[i], av[i]);
                acc[i][0] = ffma2(ai, bp0, acc[i][0]);
                acc[i][1] = ffma2(ai, bp1, acc[i][1]);
                acc[i][2] = ffma2(ai, bp2, acc[i][2]);
                acc[i][3] = ffma2(ai, bp3, acc[i][3]);
            }
        }
        if (t + 1 < T) {
            __syncthreads();
            store_tile((t + 1) & 1, ra, rb);
            __syncthreads();
        }
    }

    float bl[4], bh[4];
#pragma unroll
    for (int jp = 0; jp < 4; jp++) {
        int col = n0 + tx * 8 + jp * 2;
        bl[jp] = (col < N) ? bias[col] : 0.f;
        bh[jp] = (col + 1 < N) ? bias[col + 1] : 0.f;
    }
#pragma unroll
    for (int i = 0; i < 8; i++) {
        int row = row0 + ty * 8 + i;
        size_t obase;
        const float* rbase = nullptr;
        if (EPI == 1) {
            int bwin = row >> 8, tt = row & 255;
            int ww = bwin & 7, wh = (bwin >> 3) & 7, wd = (bwin >> 6) & 1, wn = bwin >> 7;
            int iw = tt & 7, ih = (tt >> 3) & 7, id = (tt >> 6) & 1, inn = tt >> 7;
            int n_ = wn * 2 + inn, d_ = wd * 2 + id, h_ = wh * 8 + ih, w_ = ww * 8 + iw;
            int gidx = ((n_ * 4 + d_) * 64 + h_) * 64 + w_;
            obase = (size_t)gidx * 120;
            rbase = resid + obase;
        } else {
            obase = (size_t)row * ldo;
            if (EPI == 2) rbase = resid + obase;
        }
#pragma unroll
        for (int jp = 0; jp < 4; jp++) {
            int col = n0 + tx * 8 + jp * 2;
            if (col >= N) continue;
            float lo, hi;
            upk2(acc[i][jp], lo, hi);
            lo += bl[jp]; hi += bh[jp];
            if (EPI == 0) {
                if (col + 1 < N) {
                    float2 v = {lo, hi};
                    *(float2*)&Cout[obase + col_off + col] = v;
                } else {
                    Cout[obase + col_off + col] = lo;
                }
            } else {
                if (col + 1 < N) {
                    float2 r = *(const float2*)&rbase[col];
                    float2 v = {r.x + lo, r.y + hi};
                    *(float2*)&Cout[obase + col] = v;
                } else {
                    Cout[obase + col] = rbase[col] + lo;
                }
            }
        }
    }
}

// ---------------- attention core: 2 queries per thread ----------------
// out_col_off must INCLUDE the per-head offset h*20.
__device__ __forceinline__ void attn_core(
    const float* __restrict__ qkv, float* __restrict__ out,
    const float* Ks, const float* Vs,
    int base, int qcol, int q_row_off, int o_row_off,
    int q0, int q1, int nk, int out_col_off)
{
    const float scale = 0.22360679774997896f;  // 20^-0.5
    u64 q2[2][10], o2[2][10];
    const float* qr0 = qkv + (size_t)(base + q_row_off + q0) * 720 + qcol;
    const float* qr1 = qkv + (size_t)(base + q_row_off + q1) * 720 + qcol;
#pragma unroll
    for (int t = 0; t < 5; t++) {
        float4 a = *(const float4*)(qr0 + t * 4);
        float4 b = *(const float4*)(qr1 + t * 4);
        q2[0][2 * t]     = pk2(a.x * scale, a.y * scale);
        q2[0][2 * t + 1] = pk2(a.z * scale, a.w * scale);
        q2[1][2 * t]     = pk2(b.x * scale, b.y * scale);
        q2[1][2 * t + 1] = pk2(b.z * scale, b.w * scale);
#pragma unroll
        for (int qq = 0; qq < 2; qq++) { o2[qq][2 * t] = 0ull; o2[qq][2 * t + 1] = 0ull; }
    }
    float m[2] = {-1e30f, -1e30f}, l[2] = {0.f, 0.f};

    for (int j0 = 0; j0 < nk; j0 += 8) {
        float s[2][8];
#pragma unroll
        for (int jj = 0; jj < 8; jj++) {
            const float* kr = &Ks[(j0 + jj) * 20];
            u64 kp[10];
#pragma unroll
            for (int t = 0; t < 5; t++) {
                float4 kv = *(const float4*)(kr + t * 4);
                kp[2 * t] = pk2(kv.x, kv.y);
                kp[2 * t + 1] = pk2(kv.z, kv.w);
            }
#pragma unroll
            for (int qq = 0; qq < 2; qq++) {
                u64 acc = 0ull;
#pragma unroll
                for (int t = 0; t < 10; t++) acc = ffma2(q2[qq][t], kp[t], acc);
                float lo, hi; upk2(acc, lo, hi);
                s[qq][jj] = lo + hi;
            }
        }
        float p[2][8], f[2];
#pragma unroll
        for (int qq = 0; qq < 2; qq++) {
            float cm = s[qq][0];
#pragma unroll
            for (int jj = 1; jj < 8; jj++) cm = fmaxf(cm, s[qq][jj]);
            float mn = fmaxf(m[qq], cm);
            f[qq] = __expf(m[qq] - mn);
            float ls = 0.f;
#pragma unroll
            for (int jj = 0; jj < 8; jj++) { p[qq][jj] = __expf(s[qq][jj] - mn); ls += p[qq][jj]; }
            l[qq] = l[qq] * f[qq] + ls;
            m[qq] = mn;
            u64 f2 = pk2(f[qq], f[qq]);
#pragma unroll
            for (int t = 0; t < 10; t++) o2[qq][t] = fmul2(o2[qq][t], f2);
        }
#pragma unroll
        for (int jj = 0; jj < 8; jj++) {
            const float* vr = &Vs[(j0 + jj) * 20];
            u64 vp[10];
#pragma unroll
            for (int t = 0; t < 5; t++) {
                float4 v = *(const float4*)(vr + t * 4);
                vp[2 * t] = pk2(v.x, v.y);
                vp[2 * t + 1] = pk2(v.z, v.w);
            }
            u64 pa = pk2(p[0][jj], p[0][jj]);
            u64 pb = pk2(p[1][jj], p[1][jj]);
#pragma unroll
            for (int t = 0; t < 10; t++) {
                o2[0][t] = ffma2(pa, vp[t], o2[0][t]);
                o2[1][t] = ffma2(pb, vp[t], o2[1][t]);
            }
        }
    }
#pragma unroll
    for (int qq = 0; qq < 2; qq++) {
        float inv = 1.f / l[qq];
        u64 inv2 = pk2(inv, inv);
        int qi = qq == 0 ? q0 : q1;
        float* op = out + (size_t)(base + o_row_off + qi) * 240 + out_col_off;
#pragma unroll
        for (int t = 0; t < 10; t++) {
            float lo, hi; upk2(fmul2(o2[qq][t], inv2), lo, hi);
            float2 v = {lo, hi};
            *(float2*)&op[2 * t] = v;
        }
    }
}

// ---------------- self attention: 128 threads, 2 queries/thread ----------------
__global__ void __launch_bounds__(128, 3) attn_self_kernel(
    const float* __restrict__ qkv, float* __restrict__ out)
{
    __shared__ float Ks[256 * 20];
    __shared__ float Vs[256 * 20];
    int bwin = blockIdx.x, h = blockIdx.y;
    int base = bwin * 256;
    int tid = threadIdx.x;
    int qcol = h * 20, kcol = 120 + h * 20, vcol = 240 + h * 20;

    for (int i4 = tid; i4 < 256 * 5; i4 += 128) {
        int r = i4 / 5, c4 = i4 % 5;
        size_t rowidx = (size_t)(base + r) * 720;
        *(float4*)&Ks[r * 20 + c4 * 4] = *(const float4*)&qkv[rowidx + kcol + c4 * 4];
        *(float4*)&Vs[r * 20 + c4 * 4] = *(const float4*)&qkv[rowidx + vcol + c4 * 4];
    }
    __syncthreads();
    // self outputs go to cols 120..239, head h at 120 + h*20
    attn_core(qkv, out, Ks, Vs, base, qcol, 0, 0, tid, tid + 128, 256, 120 + h * 20);
}

// ---------------- mutual attention fused: group 0 = x1(q2,k1,v1), group 1 = x2(q1,k2,v2) ----------------
__global__ void __launch_bounds__(128, 3) attn_mut_kernel(
    const float* __restrict__ qkv, float* __restrict__ out)
{
    __shared__ float K1[128 * 20], V1[128 * 20];
    __shared__ float K2[128 * 20], V2[128 * 20];
    int bwin = blockIdx.x, h = blockIdx.y;
    int base = bwin * 256;
    int tid = threadIdx.x;
    int grp = tid >> 6, ltid = tid & 63;
    int qcol = 360 + h * 20, kcol = 360 + 120 + h * 20, vcol = 360 + 240 + h * 20;

    float* Ks = grp ? K2 : K1;
    float* Vs = grp ? V2 : V1;
    int kv_off = grp ? 128 : 0;
    for (int i4 = ltid; i4 < 128 * 5; i4 += 64) {
        int r = i4 / 5, c4 = i4 % 5;
        size_t rowidx = (size_t)(base + kv_off + r) * 720;
        *(float4*)&Ks[r * 20 + c4 * 4] = *(const float4*)&qkv[rowidx + kcol + c4 * 4];
        *(float4*)&Vs[r * 20 + c4 * 4] = *(const float4*)&qkv[rowidx + vcol + c4 * 4];
    }
    __syncthreads();
    int q_row_off = grp ? 0 : 128;   // x1 uses q2 (rows 128+), x2 uses q1 (rows 0+)
    int o_row_off = grp ? 128 : 0;   // x1 -> rows 0..127, x2 -> rows 128..255
    // mutual outputs go to cols 0..119, head h at h*20
    attn_core(qkv, out, Ks, Vs, base, qcol, q_row_off, o_row_off, ltid, ltid + 64, 128, h * 20);
}

// ---------------- GEGLU gate: hid = gelu_exact(g) * u ----------------
__global__ void gate_kernel(const float* __restrict__ t, float* __restrict__ out, int total)
{
    int i = blockIdx.x * blockDim.x + threadIdx.x;
    if (i >= total) return;
    int row = i / 240, j = i % 240;
    float g = t[(size_t)row * 480 + j];
    float u = t[(size_t)row * 480 + 240 + j];
    float ge = 0.5f * g * (1.f + erff(g * 0.70710678118654752f));
    out[i] = ge * u;
}

extern "C" void kernel_launch(void* const* d_in, const int* in_sizes, int n_in,
                              void* d_out, int out_size)
{
    const float* x          = (const float*)d_in[0];
    const float* norm1_w    = (const float*)d_in[1];
    const float* norm1_b    = (const float*)d_in[2];
    const float* qkv_self_w = (const float*)d_in[3];
    const float* qkv_self_b = (const float*)d_in[4];
    const float* qkv_mut_w  = (const float*)d_in[5];
    const float* qkv_mut_b  = (const float*)d_in[6];
    const float* proj_w     = (const float*)d_in[7];
    const float* proj_b     = (const float*)d_in[8];
    const float* norm2_w    = (const float*)d_in[9];
    const float* norm2_b    = (const float*)d_in[10];
    const float* fc11_w     = (const float*)d_in[11];
    const float* fc11_b     = (const float*)d_in[12];
    const float* fc12_w     = (const float*)d_in[13];
    const float* fc12_b     = (const float*)d_in[14];
    const float* fc2_w      = (const float*)d_in[15];
    const float* fc2_b      = (const float*)d_in[16];

    float *bufA, *bufB, *bufC, *xres;
    cudaGetSymbolAddress((void**)&bufA, g_bufA);
    cudaGetSymbolAddress((void**)&bufB, g_bufB);
    cudaGetSymbolAddress((void**)&bufC, g_bufC);
    cudaGetSymbolAddress((void**)&xres, g_xres);

    const int M = TOKENS;

    // 1) LN1 + window partition -> bufC (xw)
    ln_kernel<<<M / 8, 256>>>(x, norm1_w, norm1_b, bufC, 1);

    // 2) qkv_self / qkv_mut GEMMs -> bufA [M,720]
    {
        dim3 g(M / BM, 3);
        gemm_kernel<0><<<g, 256>>>(bufC, qkv_self_w, qkv_self_b, bufA, nullptr, 360, 120, 720, 0);
        gemm_kernel<0><<<g, 256>>>(bufC, qkv_mut_w,  qkv_mut_b,  bufA, nullptr, 360, 120, 720, 360);
    }

    // 3) attention -> bufB [M,240] (cols 0..119 mutual, 120..239 self)
    attn_self_kernel<<<dim3(512, 6), 128>>>(bufA, bufB);
    attn_mut_kernel<<<dim3(512, 6), 128>>>(bufA, bufB);

    // 4) proj GEMM + window reverse + residual -> xres [M,120] (original layout)
    {
        dim3 g(M / BM, 1);
        gemm_kernel<1><<<g, 256>>>(bufB, proj_w, proj_b, xres, x, 120, 240, 120, 0);
    }

    // 5) LN2 -> bufC (h2)
    ln_kernel<<<M / 8, 256>>>(xres, norm2_w, norm2_b, bufC, 0);

    // 6) fc11 / fc12 GEMMs -> bufA [M,480]
    {
        dim3 g(M / BM, 2);
        gemm_kernel<0><<<g, 256>>>(bufC, fc11_w, fc11_b, bufA, nullptr, 240, 120, 480, 0);
        gemm_kernel<0><<<g, 256>>>(bufC, fc12_w, fc12_b, bufA, nullptr, 240, 120, 480, 240);
    }

    // 7) GEGLU gate -> bufB [M,240]
    {
        int total = M * 240;
        gate_kernel<<<(total + 255) / 256, 256>>>(bufA, bufB, total);
    }

    // 8) fc2 GEMM + residual -> d_out
    {
        dim3 g(M / BM, 1);
        gemm_kernel<2><<<g, 256>>>(bufB, fc2_w, fc2_b, (float*)d_out, xres, 120, 240, 120, 0);
    }
}